// round 1
// baseline (speedup 1.0000x reference)
#include <cuda_runtime.h>
#include <math.h>

#define BB 2
#define NN 4096
#define CD 64
#define NTH 128
#define MAXL 1024

// output layout offsets (floats), concatenated in reference return order
#define EXPOFF  0ull
#define DISPOFF 24576ull
#define POFF    49152ull
#define CONFOFF 33603584ull
#define ENTOFF  33611776ull
#define SRCPOFF 33619968ull

// scratch
__device__ float g_ssq[BB*NN];
__device__ float g_tsq[BB*NN];
__device__ float g_su[BB*NN];
__device__ float g_tu[BB*NN];
__device__ float g_lml[BB*NN];
__device__ float g_smatch[BB*NN];
__device__ float g_sdt[(size_t)BB*NN*CD];
__device__ float g_tdt[(size_t)BB*NN*CD];

__device__ __forceinline__ float lin16(int v) {
    return (float)(2*v - 15) * (1.0f/15.0f);
}

__device__ __forceinline__ float warpRedMax(float v){
    #pragma unroll
    for (int o = 16; o; o >>= 1) v = fmaxf(v, __shfl_xor_sync(0xffffffffu, v, o));
    return v;
}
__device__ __forceinline__ float warpRedMin(float v){
    #pragma unroll
    for (int o = 16; o; o >>= 1) v = fminf(v, __shfl_xor_sync(0xffffffffu, v, o));
    return v;
}
__device__ __forceinline__ float warpRedSum(float v){
    #pragma unroll
    for (int o = 16; o; o >>= 1) v += __shfl_xor_sync(0xffffffffu, v, o);
    return v;
}
__device__ __forceinline__ int warpRedSumI(int v){
    #pragma unroll
    for (int o = 16; o; o >>= 1) v += __shfl_xor_sync(0xffffffffu, v, o);
    return v;
}

// 128-thread block reductions; sred is a shared float[4] / int[4]
__device__ __forceinline__ float blockRedMax(float v, float* sred){
    v = warpRedMax(v);
    __syncthreads();
    if ((threadIdx.x & 31) == 0) sred[threadIdx.x >> 5] = v;
    __syncthreads();
    return fmaxf(fmaxf(sred[0], sred[1]), fmaxf(sred[2], sred[3]));
}
__device__ __forceinline__ float blockRedMin(float v, float* sred){
    v = warpRedMin(v);
    __syncthreads();
    if ((threadIdx.x & 31) == 0) sred[threadIdx.x >> 5] = v;
    __syncthreads();
    return fminf(fminf(sred[0], sred[1]), fminf(sred[2], sred[3]));
}
__device__ __forceinline__ float blockRedSum(float v, float* sred){
    v = warpRedSum(v);
    __syncthreads();
    if ((threadIdx.x & 31) == 0) sred[threadIdx.x >> 5] = v;
    __syncthreads();
    return (sred[0] + sred[1]) + (sred[2] + sred[3]);
}
__device__ __forceinline__ int blockRedSumI(int v, int* sred){
    v = warpRedSumI(v);
    __syncthreads();
    if ((threadIdx.x & 31) == 0) sred[threadIdx.x >> 5] = v;
    __syncthreads();
    return (sred[0] + sred[1]) + (sred[2] + sred[3]);
}

__global__ __launch_bounds__(256)
void kprep(const float* __restrict__ srcc, const float* __restrict__ tgtc,
           const float* __restrict__ sdesc, const float* __restrict__ tdesc,
           const float* __restrict__ sml, const float* __restrict__ tml,
           const float* __restrict__ sunc, const float* __restrict__ tunc,
           float* __restrict__ out_srcpos)
{
    int idx = blockIdx.x * blockDim.x + threadIdx.x;
    if (idx >= BB*NN) return;
    int b = idx / NN, n = idx % NN;

    const float* scp = srcc + (size_t)b*3*NN;
    float s0 = scp[n], s1 = scp[NN+n], s2 = scp[2*NN+n];
    g_ssq[idx] = fmaf(s2, s2, fmaf(s1, s1, s0*s0));

    const float* tcp = tgtc + (size_t)b*3*NN;
    float t0 = tcp[n], t1 = tcp[NN+n], t2 = tcp[2*NN+n];
    g_tsq[idx] = fmaf(t2, t2, fmaf(t1, t1, t0*t0));

    const float* sm = sml + (size_t)b*2*NN;
    g_smatch[idx] = 1.0f / (1.0f + expf(sm[NN+n] - sm[n]));
    const float* tm = tml + (size_t)b*2*NN;
    float p0 = 1.0f / (1.0f + expf(tm[NN+n] - tm[n]));
    g_lml[idx] = fmaxf(logf(p0), -20.0f);

    g_su[idx] = sunc[idx];
    g_tu[idx] = tunc[idx];

    // transpose descriptors: (B,C,N) -> (B,N,C) row-major
    const float* sdp = sdesc + (size_t)b*CD*NN + n;
    const float* tdp = tdesc + (size_t)b*CD*NN + n;
    float* so = g_sdt + (size_t)idx*CD;
    float* to = g_tdt + (size_t)idx*CD;
    #pragma unroll
    for (int c = 0; c < CD; c++) {
        so[c] = sdp[(size_t)c*NN];
        to[c] = tdp[(size_t)c*NN];
    }

    // src_pos output (constant voxel grid broadcast)
    int d = n >> 8, h = (n >> 4) & 15, w = n & 15;
    out_srcpos[(size_t)idx*3 + 0] = lin16(d);
    out_srcpos[(size_t)idx*3 + 1] = lin16(h);
    out_srcpos[(size_t)idx*3 + 2] = lin16(w);
}

__global__ __launch_bounds__(NTH)
void kmain(const float* __restrict__ srcc, const float* __restrict__ tgtc,
           float* __restrict__ out)
{
    const int i = blockIdx.x;
    const int b = blockIdx.y;
    const int t = threadIdx.x;
    const int bi = b*NN + i;

    __shared__ float s_sd[CD];
    __shared__ float s_red[4];
    __shared__ int   s_redi[4];
    __shared__ int   s_m;
    __shared__ int   s_list[MAXL];
    __shared__ float s_dist[MAXL];
    __shared__ float s_scr[MAXL];

    if (t < CD) s_sd[t] = g_sdt[(size_t)bi*CD + t];
    if (t == 0) s_m = 0;

    float sc0 = srcc[(size_t)b*3*NN + i];
    float sc1 = srcc[(size_t)b*3*NN + NN + i];
    float sc2 = srcc[(size_t)b*3*NN + 2*NN + i];
    float ssq = g_ssq[bi];

    const float* tcp  = tgtc + (size_t)b*3*NN;
    const float* tsqp = g_tsq + b*NN;

    // ---- phase 1: d2 row in registers, radius mask, count ----
    float d2v[32];
    unsigned radm = 0;
    int myCnt = 0;
    #pragma unroll
    for (int s = 0; s < 32; s++) {
        int j = t + s*NTH;
        float u0 = tcp[j], u1 = tcp[NN+j], u2 = tcp[2*NN+j];
        float dot = fmaf(sc2, u2, fmaf(sc1, u1, sc0*u0));
        float d2  = fmaf(-2.0f, dot, ssq + tsqp[j]);
        d2v[s] = d2;
        float dist = sqrtf(fmaxf(d2, 1e-12f));
        if (dist <= 0.45f) { radm |= (1u << s); myCnt++; }
    }
    __syncthreads();   // s_sd / s_m ready; also protects s_redi
    int cnt = blockRedSumI(myCnt, s_redi);

    // ---- phase 2: exact 24th-smallest threshold (only if radius < 24) ----
    float thr2 = -3.4e38f;
    if (cnt < 24) {
        float last = -3.4e38f;
        int need = 24 - cnt;
        for (int k = 0; k < need; k++) {
            float lmin = 3.4e38f;
            #pragma unroll
            for (int s = 0; s < 32; s++)
                if (!((radm >> s) & 1) && d2v[s] > last) lmin = fminf(lmin, d2v[s]);
            last = blockRedMin(lmin, s_red);
        }
        thr2 = last;
    }

    // ---- phase 3: zero probs row (coalesced), collect allowed ----
    float* prow = out + POFF + (size_t)bi * NN;
    #pragma unroll
    for (int s = 0; s < 32; s++) prow[t + s*NTH] = 0.0f;

    #pragma unroll
    for (int s = 0; s < 32; s++) {
        bool allowed = ((radm >> s) & 1) || (d2v[s] <= thr2);
        if (allowed) {
            int l = atomicAdd(&s_m, 1);
            if (l < MAXL) {
                s_list[l] = t + s*NTH;
                s_dist[l] = sqrtf(fmaxf(d2v[s], 1e-12f));
            }
        }
    }
    __syncthreads();
    int m = min(s_m, MAXL);

    // ---- phase 4: sparse sim + scores ----
    float su = g_su[bi];
    const float* tdb = g_tdt + (size_t)b*NN*CD;
    for (int l = t; l < m; l += NTH) {
        int j = s_list[l];
        const float4* td4 = (const float4*)(tdb + (size_t)j*CD);
        const float4* sd4 = (const float4*)s_sd;
        float a0 = 0.f, a1 = 0.f, a2 = 0.f, a3 = 0.f;
        #pragma unroll
        for (int c = 0; c < CD/4; c++) {
            float4 x = sd4[c], y = td4[c];
            a0 = fmaf(x.x, y.x, a0);
            a1 = fmaf(x.y, y.y, a1);
            a2 = fmaf(x.z, y.z, a2);
            a3 = fmaf(x.w, y.w, a3);
        }
        float sim = (a0 + a1) + (a2 + a3);
        int jj = b*NN + j;
        s_scr[l] = sim - s_dist[l] - 0.1f*(su + g_tu[jj]) + g_lml[jj];
    }
    __syncthreads();

    // ---- phase 5: softmax stats ----
    float lm = -3.4e38f;
    for (int l = t; l < m; l += NTH) lm = fmaxf(lm, s_scr[l]);
    float M = blockRedMax(lm, s_red);

    const float tinv = 1.0f / 0.07f;
    float pS = 0.f, pW = 0.f, pV0 = 0.f, pV1 = 0.f, pV2 = 0.f;
    for (int l = t; l < m; l += NTH) {
        float z = (s_scr[l] - M) * tinv;
        float e = expf(z);
        s_scr[l] = e;
        pS += e;
        pW += e * z;
        int j = s_list[l];
        pV0 += e * lin16(j >> 8);
        pV1 += e * lin16((j >> 4) & 15);
        pV2 += e * lin16(j & 15);
    }
    float S  = blockRedSum(pS,  s_red);
    float W  = blockRedSum(pW,  s_red);
    float V0 = blockRedSum(pV0, s_red);
    float V1 = blockRedSum(pV1, s_red);
    float V2 = blockRedSum(pV2, s_red);

    float invS = 1.0f / S;

    // ---- phase 6: write normalized probs (scattered, few) + outputs ----
    for (int l = t; l < m; l += NTH) prow[s_list[l]] = s_scr[l] * invS;

    if (t == 0) {
        float e0 = V0 * invS, e1 = V1 * invS, e2 = V2 * invS;
        out[EXPOFF + (size_t)bi*3 + 0] = e0;
        out[EXPOFF + (size_t)bi*3 + 1] = e1;
        out[EXPOFF + (size_t)bi*3 + 2] = e2;
        float q0 = lin16(i >> 8), q1 = lin16((i >> 4) & 15), q2 = lin16(i & 15);
        out[DISPOFF + (size_t)b*3*NN + 0*NN + i] = e0 - q0;
        out[DISPOFF + (size_t)b*3*NN + 1*NN + i] = e1 - q1;
        out[DISPOFF + (size_t)b*3*NN + 2*NN + i] = e2 - q2;
        out[CONFOFF + bi] = g_smatch[bi] * invS;   // max prob is exactly 1/S
        out[ENTOFF  + bi] = logf(S) - W * invS;
    }
}

extern "C" void kernel_launch(void* const* d_in, const int* in_sizes, int n_in,
                              void* d_out, int out_size)
{
    const float* srcc  = (const float*)d_in[0];
    const float* tgtc  = (const float*)d_in[1];
    const float* sdesc = (const float*)d_in[2];
    const float* tdesc = (const float*)d_in[3];
    const float* sml   = (const float*)d_in[4];
    const float* tml   = (const float*)d_in[5];
    const float* sunc  = (const float*)d_in[6];
    const float* tunc  = (const float*)d_in[7];
    float* out = (float*)d_out;

    kprep<<<(BB*NN + 255)/256, 256>>>(srcc, tgtc, sdesc, tdesc, sml, tml,
                                      sunc, tunc, out + SRCPOFF);
    dim3 grid(NN, BB);
    kmain<<<grid, NTH>>>(srcc, tgtc, out);
}

// round 2
// speedup vs baseline: 1.6796x; 1.6796x over previous
#include <cuda_runtime.h>
#include <math.h>

#define BB 2
#define NN 4096
#define CD 64
#define NTH 128
#define MAXL 1024

// output layout offsets (floats), concatenated in reference return order
#define EXPOFF  0ull
#define DISPOFF 24576ull
#define POFF    49152ull
#define CONFOFF 33603584ull
#define ENTOFF  33611776ull
#define SRCPOFF 33619968ull

// scratch
__device__ float g_ssq[BB*NN];
__device__ float g_tsq[BB*NN];
__device__ float g_tadd[BB*NN];    // lml_j - 0.1*tu_j folded
__device__ float g_smatch[BB*NN];
__device__ float g_sdt[(size_t)BB*NN*CD];
__device__ float g_tdt[(size_t)BB*NN*CD];

__device__ __forceinline__ float lin16(int v) {
    return (float)(2*v - 15) * (1.0f/15.0f);
}

__device__ __forceinline__ float warpRedMax(float v){
    #pragma unroll
    for (int o = 16; o; o >>= 1) v = fmaxf(v, __shfl_xor_sync(0xffffffffu, v, o));
    return v;
}
__device__ __forceinline__ float warpRedMin(float v){
    #pragma unroll
    for (int o = 16; o; o >>= 1) v = fminf(v, __shfl_xor_sync(0xffffffffu, v, o));
    return v;
}
__device__ __forceinline__ float warpRedSum(float v){
    #pragma unroll
    for (int o = 16; o; o >>= 1) v += __shfl_xor_sync(0xffffffffu, v, o);
    return v;
}
__device__ __forceinline__ int warpRedSumI(int v){
    #pragma unroll
    for (int o = 16; o; o >>= 1) v += __shfl_xor_sync(0xffffffffu, v, o);
    return v;
}

__device__ __forceinline__ float blockRedMax(float v, float* sred){
    v = warpRedMax(v);
    __syncthreads();
    if ((threadIdx.x & 31) == 0) sred[threadIdx.x >> 5] = v;
    __syncthreads();
    return fmaxf(fmaxf(sred[0], sred[1]), fmaxf(sred[2], sred[3]));
}
__device__ __forceinline__ float blockRedMin(float v, float* sred){
    v = warpRedMin(v);
    __syncthreads();
    if ((threadIdx.x & 31) == 0) sred[threadIdx.x >> 5] = v;
    __syncthreads();
    return fminf(fminf(sred[0], sred[1]), fminf(sred[2], sred[3]));
}
__device__ __forceinline__ float blockRedSum(float v, float* sred){
    v = warpRedSum(v);
    __syncthreads();
    if ((threadIdx.x & 31) == 0) sred[threadIdx.x >> 5] = v;
    __syncthreads();
    return (sred[0] + sred[1]) + (sred[2] + sred[3]);
}
__device__ __forceinline__ int blockRedSumI(int v, int* sred){
    v = warpRedSumI(v);
    __syncthreads();
    if ((threadIdx.x & 31) == 0) sred[threadIdx.x >> 5] = v;
    __syncthreads();
    return (sred[0] + sred[1]) + (sred[2] + sred[3]);
}

__global__ __launch_bounds__(256)
void kprep(const float* __restrict__ srcc, const float* __restrict__ tgtc,
           const float* __restrict__ sdesc, const float* __restrict__ tdesc,
           const float* __restrict__ sml, const float* __restrict__ tml,
           const float* __restrict__ tunc,
           float* __restrict__ out_srcpos)
{
    int idx = blockIdx.x * blockDim.x + threadIdx.x;
    if (idx >= BB*NN) return;
    int b = idx / NN, n = idx % NN;

    const float* scp = srcc + (size_t)b*3*NN;
    float s0 = scp[n], s1 = scp[NN+n], s2 = scp[2*NN+n];
    g_ssq[idx] = fmaf(s2, s2, fmaf(s1, s1, s0*s0));

    const float* tcp = tgtc + (size_t)b*3*NN;
    float t0 = tcp[n], t1 = tcp[NN+n], t2 = tcp[2*NN+n];
    g_tsq[idx] = fmaf(t2, t2, fmaf(t1, t1, t0*t0));

    const float* sm = sml + (size_t)b*2*NN;
    g_smatch[idx] = 1.0f / (1.0f + expf(sm[NN+n] - sm[n]));
    const float* tm = tml + (size_t)b*2*NN;
    float p0 = 1.0f / (1.0f + expf(tm[NN+n] - tm[n]));
    g_tadd[idx] = fmaxf(logf(p0), -20.0f) - 0.1f * tunc[idx];

    // transpose descriptors: (B,C,N) -> (B,N,C) row-major, float4 writes
    const float* sdp = sdesc + (size_t)b*CD*NN + n;
    const float* tdp = tdesc + (size_t)b*CD*NN + n;
    float4* so = (float4*)(g_sdt + (size_t)idx*CD);
    float4* to = (float4*)(g_tdt + (size_t)idx*CD);
    #pragma unroll
    for (int c4 = 0; c4 < CD/4; c4++) {
        float4 v, w;
        v.x = sdp[(size_t)(4*c4+0)*NN]; w.x = tdp[(size_t)(4*c4+0)*NN];
        v.y = sdp[(size_t)(4*c4+1)*NN]; w.y = tdp[(size_t)(4*c4+1)*NN];
        v.z = sdp[(size_t)(4*c4+2)*NN]; w.z = tdp[(size_t)(4*c4+2)*NN];
        v.w = sdp[(size_t)(4*c4+3)*NN]; w.w = tdp[(size_t)(4*c4+3)*NN];
        so[c4] = v;
        to[c4] = w;
    }

    // src_pos output (constant voxel grid broadcast)
    int d = n >> 8, h = (n >> 4) & 15, w = n & 15;
    out_srcpos[(size_t)idx*3 + 0] = lin16(d);
    out_srcpos[(size_t)idx*3 + 1] = lin16(h);
    out_srcpos[(size_t)idx*3 + 2] = lin16(w);
}

__global__ __launch_bounds__(NTH)
void kmain(const float* __restrict__ srcc, const float* __restrict__ tgtc,
           float* __restrict__ out)
{
    const int i = blockIdx.x;
    const int b = blockIdx.y;
    const int t = threadIdx.x;
    const int lane = t & 31;
    const int warp = t >> 5;
    const int bi = b*NN + i;

    __shared__ float s_sd[CD];
    __shared__ float s_red[4];
    __shared__ int   s_redi[4];
    __shared__ int   s_w[4];
    __shared__ int   s_list[MAXL];
    __shared__ float s_d2l[MAXL];
    __shared__ float s_scr[MAXL];

    // ---- phase 0: zero probs row early (fire-and-forget DRAM writes) ----
    float* prow = out + POFF + (size_t)bi * NN;
    {
        float4 z4 = make_float4(0.f, 0.f, 0.f, 0.f);
        float4* p4 = (float4*)prow;
        #pragma unroll
        for (int s = 0; s < 8; s++) p4[t + s*NTH] = z4;
    }

    if (t < CD) s_sd[t] = g_sdt[(size_t)bi*CD + t];

    // exact float boundary T_rad: largest t with sqrtf(t) <= 0.45f
    float radThr;
    {
        const float R = 0.45f;
        float tt = R * R;
        while (sqrtf(tt) > R) tt = __uint_as_float(__float_as_uint(tt) - 1u);
        while (sqrtf(__uint_as_float(__float_as_uint(tt) + 1u)) <= R)
            tt = __uint_as_float(__float_as_uint(tt) + 1u);
        radThr = tt;
    }

    float sc0 = srcc[(size_t)b*3*NN + i];
    float sc1 = srcc[(size_t)b*3*NN + NN + i];
    float sc2 = srcc[(size_t)b*3*NN + 2*NN + i];
    float ssq = g_ssq[bi];

    const float* tcp  = tgtc + (size_t)b*3*NN;
    const float* tsqp = g_tsq + b*NN;

    // ---- phase 1: clamped d2 row in registers (NO sqrt), radius count ----
    float d2v[32];
    int myCnt = 0;
    #pragma unroll
    for (int s = 0; s < 32; s++) {
        int j = t + s*NTH;
        float u0 = tcp[j], u1 = tcp[NN+j], u2 = tcp[2*NN+j];
        float dot = fmaf(sc2, u2, fmaf(sc1, u1, sc0*u0));
        float d2  = fmaf(-2.0f, dot, ssq + tsqp[j]);
        float d2c = fmaxf(d2, 1e-12f);
        d2v[s] = d2c;
        if (d2c <= radThr) myCnt++;
    }
    __syncthreads();   // s_sd ready; protects s_redi
    int cnt = blockRedSumI(myCnt, s_redi);

    // ---- phase 2: exact 24th-smallest d2 threshold (rare: cnt < 24) ----
    float thrAll = radThr;
    if (cnt < 24) {
        float last = -3.4e38f;
        int need = 24 - cnt;
        for (int k = 0; k < need; k++) {
            float lmin = 3.4e38f;
            #pragma unroll
            for (int s = 0; s < 32; s++)
                if (d2v[s] > radThr && d2v[s] > last) lmin = fminf(lmin, d2v[s]);
            last = blockRedMin(lmin, s_red);
        }
        thrAll = fmaxf(radThr, last);
    }

    // ---- phase 3: gather allowed via ballot-free scan compaction ----
    unsigned amask = 0;
    #pragma unroll
    for (int s = 0; s < 32; s++)
        if (d2v[s] <= thrAll) amask |= (1u << s);
    int myc = __popc(amask);

    // warp inclusive scan of counts
    int incl = myc;
    #pragma unroll
    for (int o = 1; o < 32; o <<= 1) {
        int nbr = __shfl_up_sync(0xffffffffu, incl, o);
        if (lane >= o) incl += nbr;
    }
    __syncthreads();   // protect s_w reuse
    if (lane == 31) s_w[warp] = incl;
    __syncthreads();
    int base = incl - myc;
    #pragma unroll
    for (int w = 0; w < 4; w++)
        if (w < warp) base += s_w[w];
    int m = (s_w[0] + s_w[1]) + (s_w[2] + s_w[3]);
    if (m > MAXL) m = MAXL;

    #pragma unroll
    for (int s = 0; s < 32; s++) {
        if ((amask >> s) & 1) {
            if (base < MAXL) {
                s_list[base] = t + s*NTH;
                s_d2l[base] = d2v[s];
            }
            base++;
        }
    }
    __syncthreads();

    // ---- phase 4: sparse sim + scores (sqrt only here, ~m per row) ----
    const float* tdb = g_tdt + (size_t)b*NN*CD;
    const float* tap = g_tadd + b*NN;
    for (int l = t; l < m; l += NTH) {
        int j = s_list[l];
        const float4* td4 = (const float4*)(tdb + (size_t)j*CD);
        const float4* sd4 = (const float4*)s_sd;
        float a0 = 0.f, a1 = 0.f, a2 = 0.f, a3 = 0.f;
        #pragma unroll
        for (int c = 0; c < CD/4; c++) {
            float4 x = sd4[c], y = td4[c];
            a0 = fmaf(x.x, y.x, a0);
            a1 = fmaf(x.y, y.y, a1);
            a2 = fmaf(x.z, y.z, a2);
            a3 = fmaf(x.w, y.w, a3);
        }
        float sim = (a0 + a1) + (a2 + a3);
        s_scr[l] = sim - sqrtf(s_d2l[l]) + tap[j];
    }
    __syncthreads();

    // ---- phase 5: softmax stats ----
    float lm = -3.4e38f;
    for (int l = t; l < m; l += NTH) lm = fmaxf(lm, s_scr[l]);
    float M = blockRedMax(lm, s_red);

    const float tinv = 1.0f / 0.07f;
    float pS = 0.f, pW = 0.f, pV0 = 0.f, pV1 = 0.f, pV2 = 0.f;
    for (int l = t; l < m; l += NTH) {
        float z = (s_scr[l] - M) * tinv;
        float e = expf(z);
        s_scr[l] = e;
        pS += e;
        pW += e * z;
        int j = s_list[l];
        pV0 += e * lin16(j >> 8);
        pV1 += e * lin16((j >> 4) & 15);
        pV2 += e * lin16(j & 15);
    }
    float S  = blockRedSum(pS,  s_red);
    float W  = blockRedSum(pW,  s_red);
    float V0 = blockRedSum(pV0, s_red);
    float V1 = blockRedSum(pV1, s_red);
    float V2 = blockRedSum(pV2, s_red);

    float invS = 1.0f / S;

    // ---- phase 6: write normalized probs (scattered, few) + outputs ----
    for (int l = t; l < m; l += NTH) prow[s_list[l]] = s_scr[l] * invS;

    if (t == 0) {
        float e0 = V0 * invS, e1 = V1 * invS, e2 = V2 * invS;
        out[EXPOFF + (size_t)bi*3 + 0] = e0;
        out[EXPOFF + (size_t)bi*3 + 1] = e1;
        out[EXPOFF + (size_t)bi*3 + 2] = e2;
        float q0 = lin16(i >> 8), q1 = lin16((i >> 4) & 15), q2 = lin16(i & 15);
        out[DISPOFF + (size_t)b*3*NN + 0*NN + i] = e0 - q0;
        out[DISPOFF + (size_t)b*3*NN + 1*NN + i] = e1 - q1;
        out[DISPOFF + (size_t)b*3*NN + 2*NN + i] = e2 - q2;
        out[CONFOFF + bi] = g_smatch[bi] * invS;   // max prob is exactly 1/S
        out[ENTOFF  + bi] = logf(S) - W * invS;
    }
}

extern "C" void kernel_launch(void* const* d_in, const int* in_sizes, int n_in,
                              void* d_out, int out_size)
{
    const float* srcc  = (const float*)d_in[0];
    const float* tgtc  = (const float*)d_in[1];
    const float* sdesc = (const float*)d_in[2];
    const float* tdesc = (const float*)d_in[3];
    const float* sml   = (const float*)d_in[4];
    const float* tml   = (const float*)d_in[5];
    const float* tunc  = (const float*)d_in[7];
    float* out = (float*)d_out;

    kprep<<<(BB*NN + 255)/256, 256>>>(srcc, tgtc, sdesc, tdesc, sml, tml,
                                      tunc, out + SRCPOFF);
    dim3 grid(NN, BB);
    kmain<<<grid, NTH>>>(srcc, tgtc, out);
}